// round 9
// baseline (speedup 1.0000x reference)
#include <cuda_runtime.h>

#define EPSF 1e-6f

constexpr int cV = 128, cK = 32, cC = 256;
constexpr int cL = 4, cN = 4096, cF = 16;
constexpr int cE = 8192, cB = 512;
constexpr int cB4 = cB / 4;            // 128 float4 groups per row
constexpr int NT   = 256;
constexpr int BPSM = 4;                // blocks/SM via launch_bounds
constexpr int GRID = 148 * BPSM;       // 592 persistent blocks
constexpr int NWARP = GRID * NT / 32;  // 4736 warps
constexpr float LN2F = 0.69314718055994530942f;

// ---- scratch (static __device__ per allocation rules) ----
__device__ __align__(16) float d_lwlin[cV * cK * cC];  // 4 MB linear mantissas (rowmax=1)
__device__ __align__(16) float d_eIn[cV * cK];         // 16 KB input row scales (log2)
__device__ __align__(16) int4  d_fw[cL * cN * cF];     // 4 MB {c0, c1, W, 0} raw rows
__device__ __align__(16) float d_R[cN];                // linear root weights
__device__ __align__(16) float d_eA[cN];               // layer row scales ping
__device__ __align__(16) float d_eB[cN];               // layer row scales pong
__device__ __align__(16) int   d_xT[cV * cB];          // transposed inputs
__device__ __align__(16) float d_nmA[cN * cB];         // 8 MB
__device__ __align__(16) float d_nmB[cN * cB];         // 8 MB

// ---- grid barrier state ----
__device__ unsigned d_bar_count = 0;
__device__ volatile unsigned d_bar_gen = 0;

// ---- single-instruction MUFU ops ----
__device__ __forceinline__ float ex2(float x) {
    float y; asm("ex2.approx.ftz.f32 %0, %1;" : "=f"(y) : "f"(x)); return y;
}
__device__ __forceinline__ float lg2(float x) {
    float y; asm("lg2.approx.ftz.f32 %0, %1;" : "=f"(y) : "f"(x)); return y;
}
__device__ __forceinline__ float rcp(float x) {
    float y; asm("rcp.approx.ftz.f32 %0, %1;" : "=f"(y) : "f"(x)); return y;
}

// ==================================================================
// PREP: linear mantissa input table + row scales, fused sum tables
// (raw rows + linear W), linear root weights, input transpose.
// ==================================================================
__global__ void __launch_bounds__(256) k_prep(const float* __restrict__ ip,
                                              const float* __restrict__ sp,
                                              const float* __restrict__ rp,
                                              const int*   __restrict__ inputs,
                                              const int*   __restrict__ sci,
                                              const int*   __restrict__ pc) {
    int b = blockIdx.x;
    if (b < 512) {
        // --- input params: one warp per (v,k) row of C=256 ---
        int w    = b * 8 + (threadIdx.x >> 5);
        int lane = threadIdx.x & 31;
        const float* row = ip + w * cC;
        float v[8];
        float tot = 0.f, mx = 0.f;
#pragma unroll
        for (int i = 0; i < 8; i++) {
            v[i] = row[lane + i * 32] + EPSF;
            tot += v[i];
            mx = fmaxf(mx, v[i]);
        }
#pragma unroll
        for (int o = 16; o; o >>= 1) {
            tot += __shfl_xor_sync(0xffffffffu, tot, o);
            mx = fmaxf(mx, __shfl_xor_sync(0xffffffffu, mx, o));
        }
        float inv = rcp(mx);
#pragma unroll
        for (int i = 0; i < 8; i++) d_lwlin[w * cC + lane + i * 32] = v[i] * inv;
        if (lane == 0) d_eIn[w] = lg2(mx) - lg2(tot);   // true = stored * 2^e / (норм)
    } else if (b < 576) {
        // --- fused sum tables: one thread per (l,n) ---
        int r = (b - 512) * 256 + threadIdx.x;
        int l = r / cN;
        const float* spr  = sp  + r * cF;
        const int*   scir = sci + r * cF;
        const int2*  pcl  = reinterpret_cast<const int2*>(pc) + l * cE;
        float w[cF];
        float tot = 0.f;
#pragma unroll
        for (int f = 0; f < cF; f++) { w[f] = spr[f] + EPSF; tot += w[f]; }
        float inv = 1.f / tot;
        int4* dst = d_fw + r * cF;
#pragma unroll
        for (int f = 0; f < cF; f++) {
            int2 c = pcl[scir[f]];
            dst[f] = make_int4(c.x, c.y, __float_as_int(w[f] * inv), 0);
        }
    } else if (b == 576) {
        // --- root params: linear normalize over N=4096 ---
        __shared__ float red[256];
        int t = threadIdx.x;
        float v[16];
        float s = 0.f;
#pragma unroll
        for (int i = 0; i < 16; i++) {
            v[i] = rp[t + i * 256] + EPSF;
            s += v[i];
        }
        red[t] = s;
        __syncthreads();
        for (int o = 128; o; o >>= 1) {
            if (t < o) red[t] += red[t + o];
            __syncthreads();
        }
        float inv = 1.f / red[0];
#pragma unroll
        for (int i = 0; i < 16; i++) d_R[t + i * 256] = v[i] * inv;
    } else {
        // --- transpose inputs (B,V) -> xT (V,B) ---
        int id = (b - 577) * 256 + threadIdx.x;
        for (int i = id; i < cV * cB; i += 64 * 256) {
            int bb = i >> 7;
            int vv = i & 127;
            d_xT[vv * cB + bb] = inputs[i];
        }
    }
}

// ==================================================================
// grid barrier (all GRID blocks resident).
// ==================================================================
__device__ __forceinline__ void grid_barrier() {
    __syncthreads();
    if (threadIdx.x == 0) {
        __threadfence();
        unsigned gen = d_bar_gen;
        unsigned t   = atomicAdd(&d_bar_count, 1u);
        if (t == GRID - 1) {
            d_bar_count = 0;
            __threadfence();
            d_bar_gen = gen + 1;
        } else {
            while (d_bar_gen == gen) { __nanosleep(64); }
        }
        __threadfence();
    }
    __syncthreads();
}

// ==================================================================
// PERSISTENT kernel — LINEAR-DOMAIN layers with per-row scales.
// Row n stored as mantissa[512] (rowmax-normalized) + e[n] (log2 scale).
// Layer: g_f = e[c0_f]+e[c1_f]; G = max_f g_f; coef_f = W_f*2^(g_f-G);
//        acc[b] = sum_f coef_f * a_f[b]*b_f[b];
//        store acc/rowmax, e_out = G + lg2(rowmax).
// Last layer emits log2 values directly; root LSE unchanged.
// ==================================================================
__global__ void __launch_bounds__(NT, BPSM) k_persist(float* __restrict__ out) {
    __shared__ float4 s_m[NT];
    __shared__ float4 s_s[NT];
    const int t    = threadIdx.x;
    const int lane = t & 31;
    const int wid  = (blockIdx.x * NT + t) >> 5;   // global warp id

    // ---------- phase 0: input gather (linear mantissas) -> d_nmA ----------
    {
        const int stride = GRID * NT;
        for (int i = blockIdx.x * NT + t; i < cN * cB; i += stride) {
            int b  = i & (cB - 1);
            int vk = i >> 9;
            int v  = vk >> 5;
            int x  = d_xT[v * cB + b];
            d_nmA[i] = d_lwlin[vk * cC + x];
        }
    }
    grid_barrier();

    // ---------- 4 fused linear layers ----------
    float* nm_src = d_nmA;
    float* nm_dst = d_nmB;
    const float* esrc = d_eIn;
    for (int l = 0; l < cL; l++) {
        float* edst = (l & 1) ? d_eB : d_eA;
        const int4*   fwl = d_fw + l * cN * cF;
        const float4* nmS = reinterpret_cast<const float4*>(nm_src);

        for (int task = wid; task < cN; task += NWARP) {
            const int4* fwp = fwl + task * cF;
            int4 p = __ldg(fwp + (lane & 15));          // lanes 16-31 mirror 0-15
            float g_my = __ldg(esrc + p.x) + __ldg(esrc + p.y);
            float G = g_my;
#pragma unroll
            for (int o = 1; o < 16; o <<= 1)
                G = fmaxf(G, __shfl_xor_sync(0xffffffffu, G, o));
            float coef_my = __int_as_float(p.z) * ex2(g_my - G);
            int ro0 = p.x * cB4;
            int ro1 = p.y * cB4;

            float4 acc0 = make_float4(0.f, 0.f, 0.f, 0.f);
            float4 acc1 = acc0, acc2 = acc0, acc3 = acc0;
#pragma unroll
            for (int f = 0; f < cF; f++) {
                float cf = __shfl_sync(0xffffffffu, coef_my, f);
                int o0 = __shfl_sync(0xffffffffu, ro0, f) + lane;
                int o1 = __shfl_sync(0xffffffffu, ro1, f) + lane;
                float4 a0 = nmS[o0      ], b0 = nmS[o1      ];
                float4 a1 = nmS[o0 +  32], b1 = nmS[o1 +  32];
                float4 a2 = nmS[o0 +  64], b2 = nmS[o1 +  64];
                float4 a3 = nmS[o0 +  96], b3 = nmS[o1 +  96];
                acc0.x += cf * (a0.x * b0.x); acc0.y += cf * (a0.y * b0.y);
                acc0.z += cf * (a0.z * b0.z); acc0.w += cf * (a0.w * b0.w);
                acc1.x += cf * (a1.x * b1.x); acc1.y += cf * (a1.y * b1.y);
                acc1.z += cf * (a1.z * b1.z); acc1.w += cf * (a1.w * b1.w);
                acc2.x += cf * (a2.x * b2.x); acc2.y += cf * (a2.y * b2.y);
                acc2.z += cf * (a2.z * b2.z); acc2.w += cf * (a2.w * b2.w);
                acc3.x += cf * (a3.x * b3.x); acc3.y += cf * (a3.y * b3.y);
                acc3.z += cf * (a3.z * b3.z); acc3.w += cf * (a3.w * b3.w);
            }

            float4* dst = reinterpret_cast<float4*>(nm_dst) + task * cB4 + lane;
            if (l < cL - 1) {
                // row renormalize: rowmax -> 1, fold into e_out
                float rm = fmaxf(fmaxf(fmaxf(acc0.x, acc0.y), fmaxf(acc0.z, acc0.w)),
                                 fmaxf(fmaxf(acc1.x, acc1.y), fmaxf(acc1.z, acc1.w)));
                rm = fmaxf(rm, fmaxf(fmaxf(acc2.x, acc2.y), fmaxf(acc2.z, acc2.w)));
                rm = fmaxf(rm, fmaxf(fmaxf(acc3.x, acc3.y), fmaxf(acc3.z, acc3.w)));
#pragma unroll
                for (int o = 16; o; o >>= 1)
                    rm = fmaxf(rm, __shfl_xor_sync(0xffffffffu, rm, o));
                float ri = rcp(rm);
                float4 w0, w1, w2, w3;
                w0.x = acc0.x * ri; w0.y = acc0.y * ri; w0.z = acc0.z * ri; w0.w = acc0.w * ri;
                w1.x = acc1.x * ri; w1.y = acc1.y * ri; w1.z = acc1.z * ri; w1.w = acc1.w * ri;
                w2.x = acc2.x * ri; w2.y = acc2.y * ri; w2.z = acc2.z * ri; w2.w = acc2.w * ri;
                w3.x = acc3.x * ri; w3.y = acc3.y * ri; w3.z = acc3.z * ri; w3.w = acc3.w * ri;
                dst[0] = w0; dst[32] = w1; dst[64] = w2; dst[96] = w3;
                if (lane == 0) edst[task] = G + lg2(rm);
            } else {
                // final layer: emit log2 values for the root reduction
                float4 w0, w1, w2, w3;
                w0.x = G + lg2(acc0.x); w0.y = G + lg2(acc0.y);
                w0.z = G + lg2(acc0.z); w0.w = G + lg2(acc0.w);
                w1.x = G + lg2(acc1.x); w1.y = G + lg2(acc1.y);
                w1.z = G + lg2(acc1.z); w1.w = G + lg2(acc1.w);
                w2.x = G + lg2(acc2.x); w2.y = G + lg2(acc2.y);
                w2.z = G + lg2(acc2.z); w2.w = G + lg2(acc2.w);
                w3.x = G + lg2(acc3.x); w3.y = G + lg2(acc3.y);
                w3.z = G + lg2(acc3.z); w3.w = G + lg2(acc3.w);
                dst[0] = w0; dst[32] = w1; dst[64] = w2; dst[96] = w3;
            }
        }
        grid_barrier();

        float* tmp = nm_src; nm_src = nm_dst; nm_dst = tmp;
        esrc = edst;
    }

    // ---------- root: out[b] = ln2 * (m + lg2(sum_n R_n 2^(x_nb - m))) ----------
    if (blockIdx.x < cB4) {
        const int g = blockIdx.x;              // float4 batch group
        const float4* nmp = reinterpret_cast<const float4*>(nm_src);

        float R0 = __ldg(d_R + t);
        float4 m = nmp[t * cB4 + g];
        float4 s = make_float4(R0, R0, R0, R0);
#pragma unroll
        for (int k = 1; k < cN / NT; k++) {
            int   n = t + k * NT;
            float R = __ldg(d_R + n);
            float4 x = nmp[n * cB4 + g];
            s.x += R * ex2(x.x - m.x);
            s.y += R * ex2(x.y - m.y);
            s.z += R * ex2(x.z - m.z);
            s.w += R * ex2(x.w - m.w);
        }
        s_m[t] = m; s_s[t] = s;
        __syncthreads();
        for (int o = NT / 2; o; o >>= 1) {
            if (t < o) {
                float4 m1 = s_m[t], m2 = s_m[t + o];
                float4 s1 = s_s[t], s2 = s_s[t + o];
                float4 mm, ss;
                mm.x = fmaxf(m1.x, m2.x);
                mm.y = fmaxf(m1.y, m2.y);
                mm.z = fmaxf(m1.z, m2.z);
                mm.w = fmaxf(m1.w, m2.w);
                ss.x = s1.x * ex2(m1.x - mm.x) + s2.x * ex2(m2.x - mm.x);
                ss.y = s1.y * ex2(m1.y - mm.y) + s2.y * ex2(m2.y - mm.y);
                ss.z = s1.z * ex2(m1.z - mm.z) + s2.z * ex2(m2.z - mm.z);
                ss.w = s1.w * ex2(m1.w - mm.w) + s2.w * ex2(m2.w - mm.w);
                s_m[t] = mm; s_s[t] = ss;
            }
            __syncthreads();
        }
        if (t == 0) {
            float4 m0 = s_m[0], s0 = s_s[0];
            out[g * 4 + 0] = (m0.x + lg2(s0.x)) * LN2F;
            out[g * 4 + 1] = (m0.y + lg2(s0.y)) * LN2F;
            out[g * 4 + 2] = (m0.z + lg2(s0.z)) * LN2F;
            out[g * 4 + 3] = (m0.w + lg2(s0.w)) * LN2F;
        }
    }
}

// ==================================================================
extern "C" void kernel_launch(void* const* d_in, const int* in_sizes, int n_in,
                              void* d_out, int out_size) {
    const int*   inputs = (const int*)d_in[0];    // (B, V)
    const int*   pc     = (const int*)d_in[1];    // (L, E, 2)
    const int*   sci    = (const int*)d_in[2];    // (L, N, F)
    const float* ip     = (const float*)d_in[3];  // (V, K, C)
    const float* sp     = (const float*)d_in[4];  // (L, N, F)
    const float* rp     = (const float*)d_in[5];  // (N,)
    float* out = (float*)d_out;                   // (B,)

    k_prep<<<641, 256>>>(ip, sp, rp, inputs, sci, pc);
    k_persist<<<GRID, NT>>>(out);
}

// round 10
// speedup vs baseline: 1.8558x; 1.8558x over previous
#include <cuda_runtime.h>

#define EPSF 1e-6f
#define FULLM 0xffffffffu

constexpr int cV = 128, cK = 32, cC = 256;
constexpr int cL = 4, cN = 4096, cF = 16;
constexpr int cE = 8192, cB = 512;
constexpr int cB4 = cB / 4;            // 128 float4 groups per row
constexpr int NT   = 512;
constexpr int BPSM = 2;                // blocks/SM via launch_bounds (64-reg budget)
constexpr int GRID = 148 * BPSM;       // 296 persistent blocks
constexpr int NWARP = GRID * NT / 32;  // 4736 warps
constexpr float LN2F = 0.69314718055994530942f;

// ---- scratch (static __device__ per allocation rules) ----
__device__ __align__(16) float d_lwin[cV * cK * cC];   // 4 MB (log2 domain)
__device__ __align__(16) int4  d_fw[cL * cN * cF];     // 4 MB {c0*cB4, c1*cB4, W, 0}
__device__ __align__(16) float d_R[cN];                // 16 KB linear root weights
__device__ __align__(16) int   d_xT[cV * cB];          // 256 KB transposed inputs
__device__ __align__(16) float d_nmA[cN * cB];         // 8 MB
__device__ __align__(16) float d_nmB[cN * cB];         // 8 MB

// ---- grid barrier state ----
__device__ unsigned d_bar_count = 0;
__device__ volatile unsigned d_bar_gen = 0;

// ---- single-instruction MUFU ops ----
__device__ __forceinline__ float ex2(float x) {
    float y; asm("ex2.approx.ftz.f32 %0, %1;" : "=f"(y) : "f"(x)); return y;
}
__device__ __forceinline__ float lg2(float x) {
    float y; asm("lg2.approx.ftz.f32 %0, %1;" : "=f"(y) : "f"(x)); return y;
}

// ==================================================================
// PREP: lwin (log2-normalized), FUSED sum tables {c0,c1,W}, linear
// root weights, input transpose.
// ==================================================================
__global__ void __launch_bounds__(256) k_prep(const float* __restrict__ ip,
                                              const float* __restrict__ sp,
                                              const float* __restrict__ rp,
                                              const int*   __restrict__ inputs,
                                              const int*   __restrict__ sci,
                                              const int*   __restrict__ pc) {
    int b = blockIdx.x;
    if (b < 512) {
        int w    = b * 8 + (threadIdx.x >> 5);
        int lane = threadIdx.x & 31;
        const float* row = ip + w * cC;
        float v[8];
        float m = -1e30f;
#pragma unroll
        for (int i = 0; i < 8; i++) {
            v[i] = lg2(row[lane + i * 32] + EPSF);
            m    = fmaxf(m, v[i]);
        }
#pragma unroll
        for (int o = 16; o; o >>= 1) m = fmaxf(m, __shfl_xor_sync(FULLM, m, o));
        float s = 0.f;
#pragma unroll
        for (int i = 0; i < 8; i++) s += ex2(v[i] - m);
#pragma unroll
        for (int o = 16; o; o >>= 1) s += __shfl_xor_sync(FULLM, s, o);
        float lse = m + lg2(s);
#pragma unroll
        for (int i = 0; i < 8; i++) d_lwin[w * cC + lane + i * 32] = v[i] - lse;
    } else if (b < 576) {
        // --- fused sum tables: one thread per (l,n) ---
        int r = (b - 512) * 256 + threadIdx.x;
        int l = r / cN;
        const float* spr  = sp  + r * cF;
        const int*   scir = sci + r * cF;
        const int2*  pcl  = reinterpret_cast<const int2*>(pc) + l * cE;
        float w[cF];
        float tot = 0.f;
#pragma unroll
        for (int f = 0; f < cF; f++) { w[f] = spr[f] + EPSF; tot += w[f]; }
        float inv = 1.f / tot;
        int4* dst = d_fw + r * cF;
#pragma unroll
        for (int f = 0; f < cF; f++) {
            int2 c = pcl[scir[f]];
            dst[f] = make_int4(c.x * cB4, c.y * cB4, __float_as_int(w[f] * inv), 0);
        }
    } else if (b == 576) {
        __shared__ float red[256];
        int t = threadIdx.x;
        float v[16];
        float s = 0.f;
#pragma unroll
        for (int i = 0; i < 16; i++) {
            v[i] = rp[t + i * 256] + EPSF;
            s += v[i];
        }
        red[t] = s;
        __syncthreads();
        for (int o = 128; o; o >>= 1) {
            if (t < o) red[t] += red[t + o];
            __syncthreads();
        }
        float inv = 1.f / red[0];
#pragma unroll
        for (int i = 0; i < 16; i++) d_R[t + i * 256] = v[i] * inv;
    } else {
        int id = (b - 577) * 256 + threadIdx.x;
        for (int i = id; i < cV * cB; i += 64 * 256) {
            int bb = i >> 7;
            int vv = i & 127;
            d_xT[vv * cB + bb] = inputs[i];
        }
    }
}

// ==================================================================
// grid barrier (all GRID blocks resident).
// ==================================================================
__device__ __forceinline__ void grid_barrier() {
    __syncthreads();
    if (threadIdx.x == 0) {
        __threadfence();
        unsigned gen = d_bar_gen;
        unsigned t   = atomicAdd(&d_bar_count, 1u);
        if (t == GRID - 1) {
            d_bar_count = 0;
            __threadfence();
            d_bar_gen = gen + 1;
        } else {
            while (d_bar_gen == gen) { __nanosleep(64); }
        }
        __threadfence();
    }
    __syncthreads();
}

// ==================================================================
// PERSISTENT kernel: gather -> 4x FUSED(product+sum) -> root LSE.
// float4 lanes, shfl-distributed indices, depth-2 pipelined gathers.
// ==================================================================
__global__ void __launch_bounds__(NT, BPSM) k_persist(float* __restrict__ out) {
    __shared__ float4 s_m[NT];
    __shared__ float4 s_s[NT];
    const int t    = threadIdx.x;
    const int lane = t & 31;
    const int wid  = (blockIdx.x * NT + t) >> 5;   // global warp id

    // ---------- phase 0: input gather -> d_nmA ----------
    {
        const int stride = GRID * NT;
        for (int i = blockIdx.x * NT + t; i < cN * cB; i += stride) {
            int b  = i & (cB - 1);
            int vk = i >> 9;
            int v  = vk >> 5;
            int x  = d_xT[v * cB + b];
            d_nmA[i] = d_lwin[vk * cC + x];
        }
    }
    grid_barrier();

    // ---------- 4 fused layers ----------
    float* nm_src = d_nmA;
    float* nm_dst = d_nmB;
    for (int l = 0; l < cL; l++) {
        const int4*   fwl = d_fw + l * cN * cF;
        const float4* nmp = reinterpret_cast<const float4*>(nm_src);
        for (int task = wid; task < cN * 4; task += NWARP) {
            int n = task >> 2;
            int g = ((task & 3) << 5) + lane;
            // lane f (mirrored at f+16) owns table entry f
            int4 pm = __ldg(fwl + n * cF + (lane & 15));

            // issue f=0 (shift) + slots A(f=1), B(f=2) — 6 gathers in flight
            float4 a0 = nmp[__shfl_sync(FULLM, pm.x, 0) + g];
            float4 b0 = nmp[__shfl_sync(FULLM, pm.y, 0) + g];
            float4 aA = nmp[__shfl_sync(FULLM, pm.x, 1) + g];
            float4 bA = nmp[__shfl_sync(FULLM, pm.y, 1) + g];
            float4 aB = nmp[__shfl_sync(FULLM, pm.x, 2) + g];
            float4 bB = nmp[__shfl_sync(FULLM, pm.y, 2) + g];

            float4 m;
            m.x = a0.x + b0.x; m.y = a0.y + b0.y;
            m.z = a0.z + b0.z; m.w = a0.w + b0.w;
            float W0 = __uint_as_float(__shfl_sync(FULLM, (unsigned)pm.z, 0));
            float4 s = make_float4(W0, W0, W0, W0);

#pragma unroll
            for (int f = 1; f < cF; f++) {
                float  W = __uint_as_float(__shfl_sync(FULLM, (unsigned)pm.z, f));
                float4 a = aA, b = bA;
                aA = aB; bA = bB;
                if (f + 2 < cF) {   // prefetch f+2 into slot B
                    aB = nmp[__shfl_sync(FULLM, pm.x, f + 2) + g];
                    bB = nmp[__shfl_sync(FULLM, pm.y, f + 2) + g];
                }
                s.x += W * ex2(a.x + b.x - m.x);
                s.y += W * ex2(a.y + b.y - m.y);
                s.z += W * ex2(a.z + b.z - m.z);
                s.w += W * ex2(a.w + b.w - m.w);
            }
            float4 o;
            o.x = m.x + lg2(s.x);
            o.y = m.y + lg2(s.y);
            o.z = m.z + lg2(s.z);
            o.w = m.w + lg2(s.w);
            reinterpret_cast<float4*>(nm_dst)[n * cB4 + g] = o;
        }
        grid_barrier();

        float* tmp = nm_src; nm_src = nm_dst; nm_dst = tmp;
    }

    // ---------- root: out[b] = ln2 * (m + lg2(sum_n R_n 2^(x_nb - m))) ----------
    if (blockIdx.x < cB4) {
        const int g = blockIdx.x;              // float4 batch group
        const float4* nmp = reinterpret_cast<const float4*>(nm_src);

        float R0 = __ldg(d_R + t);
        float4 m = nmp[t * cB4 + g];
        float4 s = make_float4(R0, R0, R0, R0);
#pragma unroll
        for (int k = 1; k < cN / NT; k++) {
            int   n = t + k * NT;
            float R = __ldg(d_R + n);
            float4 x = nmp[n * cB4 + g];
            s.x += R * ex2(x.x - m.x);
            s.y += R * ex2(x.y - m.y);
            s.z += R * ex2(x.z - m.z);
            s.w += R * ex2(x.w - m.w);
        }
        s_m[t] = m; s_s[t] = s;
        __syncthreads();
        for (int o = NT / 2; o; o >>= 1) {
            if (t < o) {
                float4 m1 = s_m[t], m2 = s_m[t + o];
                float4 s1 = s_s[t], s2 = s_s[t + o];
                float4 mm, ss;
                mm.x = fmaxf(m1.x, m2.x);
                mm.y = fmaxf(m1.y, m2.y);
                mm.z = fmaxf(m1.z, m2.z);
                mm.w = fmaxf(m1.w, m2.w);
                ss.x = s1.x * ex2(m1.x - mm.x) + s2.x * ex2(m2.x - mm.x);
                ss.y = s1.y * ex2(m1.y - mm.y) + s2.y * ex2(m2.y - mm.y);
                ss.z = s1.z * ex2(m1.z - mm.z) + s2.z * ex2(m2.z - mm.z);
                ss.w = s1.w * ex2(m1.w - mm.w) + s2.w * ex2(m2.w - mm.w);
                s_m[t] = mm; s_s[t] = ss;
            }
            __syncthreads();
        }
        if (t == 0) {
            float4 m0 = s_m[0], s0 = s_s[0];
            out[g * 4 + 0] = (m0.x + lg2(s0.x)) * LN2F;
            out[g * 4 + 1] = (m0.y + lg2(s0.y)) * LN2F;
            out[g * 4 + 2] = (m0.z + lg2(s0.z)) * LN2F;
            out[g * 4 + 3] = (m0.w + lg2(s0.w)) * LN2F;
        }
    }
}

// ==================================================================
extern "C" void kernel_launch(void* const* d_in, const int* in_sizes, int n_in,
                              void* d_out, int out_size) {
    const int*   inputs = (const int*)d_in[0];    // (B, V)
    const int*   pc     = (const int*)d_in[1];    // (L, E, 2)
    const int*   sci    = (const int*)d_in[2];    // (L, N, F)
    const float* ip     = (const float*)d_in[3];  // (V, K, C)
    const float* sp     = (const float*)d_in[4];  // (L, N, F)
    const float* rp     = (const float*)d_in[5];  // (N,)
    float* out = (float*)d_out;                   // (B,)

    k_prep<<<641, 256>>>(ip, sp, rp, inputs, sci, pc);
    k_persist<<<GRID, NT>>>(out);
}